// round 1
// baseline (speedup 1.0000x reference)
#include <cuda_runtime.h>
#include <math.h>

#define NB      32          // batch
#define NV      256         // vertices per polygon
#define FX      64
#define FYH     33          // FY/2+1
#define NBINS   (FX*FYH)    // 2112
#define NUFT_DIM (NBINS*2)  // 4224
#define HID     1024
#define OUTD    512

#define S1      32          // split-K for GEMM1
#define KC1     (NUFT_DIM/S1)   // 132
#define S2      16
#define KC2     (HID/S2)        // 64

// -------- device scratch (no allocations allowed) --------
__device__ float2 g_cx[NB][FX][NV];     // e^{-i pi kx vx}
__device__ float2 g_cy[NB][FYH][NV];    // e^{-i pi ky vy}
__device__ float  g_sx[NB][FX][NV];     // pi kx vx
__device__ float  g_sy[NB][FYH][NV];    // pi ky vy
__device__ float  g_C [NB][NV];         // signed origin-triangle areas
__device__ float  g_feats[NB][NUFT_DIM];
__device__ float  g_h[NB][HID];
__device__ float  g_p1[S1][NB][HID];
__device__ float  g_p2[S2][NB][OUTD];

__device__ __forceinline__ float frcp(float x) {
    float r; asm("rcp.approx.ftz.f32 %0, %1;" : "=f"(r) : "f"(x)); return r;
}

// ============================================================
// Pass 1: per (b, n) phase tables + signed areas
// ============================================================
__global__ void pass1_kernel(const float* __restrict__ P) {
    int t = blockIdx.x * blockDim.x + threadIdx.x;
    if (t >= NB * NV) return;
    int b = t >> 8, n = t & 255;
    const float PI = 3.14159265358979323846f;
    float vx = P[t * 2], vy = P[t * 2 + 1];

    #pragma unroll 4
    for (int x = 0; x < FX; x++) {
        int k = (x < 32) ? x : x - 64;
        float s = (PI * (float)k) * vx;
        float sn, cs; sincosf(s, &sn, &cs);
        g_sx[b][x][n] = s;
        g_cx[b][x][n] = make_float2(cs, -sn);
    }
    #pragma unroll 4
    for (int y = 0; y < FYH; y++) {
        float s = (PI * (float)y) * vy;
        float sn, cs; sincosf(s, &sn, &cs);
        g_sy[b][y][n] = s;
        g_cy[b][y][n] = make_float2(cs, -sn);
    }
    int n1 = (n + 1) & 255;
    float wx = P[(b * NV + n1) * 2], wy = P[(b * NV + n1) * 2 + 1];
    g_C[b][n] = 0.5f * (vx * wy - vy * wx);
}

// exact reference semantics when a denominator is 0 (rare path)
__device__ __noinline__ void slow_S(float sa, float2 ea, float sb, float2 eb,
                                    float& Sr, float& Si) {
    float dab = sa - sb;
    float den1 = dab * sa;
    float den2 = -dab * sb;
    float den3 = sa * sb;
    Sr = 0.f; Si = 0.f;
    if (den1 != 0.f) { float r = frcp(den1); Sr += ea.x * r; Si += ea.y * r; }
    if (den2 != 0.f) { float r = frcp(den2); Sr += eb.x * r; Si += eb.y * r; }
    if (den3 != 0.f) { float r = frcp(den3); Sr += r; }
}

// ============================================================
// Pass 2: NUFT spectrum -> feats (interleaved re/im)
// thread = one (b, kx, ky) bin, loops all 256 edges
// ============================================================
__global__ __launch_bounds__(128) void pass2_kernel() {
    int t = blockIdx.x * 128 + threadIdx.x;     // 0 .. 67583
    int b = t / NBINS;
    int bin = t - b * NBINS;
    int x = bin / FYH, y = bin - x * FYH;

    const float2* __restrict__ cxp = g_cx[b][x];
    const float2* __restrict__ cyp = g_cy[b][y];
    const float*  __restrict__ sxp = g_sx[b][x];
    const float*  __restrict__ syp = g_sy[b][y];
    const float*  __restrict__ Cp  = g_C[b];

    // carry = vertex NV-1 (edge 255 is 255 -> 0)
    float  sp = sxp[NV - 1] + syp[NV - 1];
    float2 a  = cxp[NV - 1], bb = cyp[NV - 1];
    float2 ep = make_float2(a.x * bb.x - a.y * bb.y, a.x * bb.y + a.y * bb.x);
    float  Cprev = Cp[NV - 1];

    float accR = 0.f, accI = 0.f;

    for (int g = 0; g < NV / 4; g++) {
        int n = 4 * g;
        float4 cx01 = *(const float4*)(cxp + n);
        float4 cx23 = *(const float4*)(cxp + n + 2);
        float4 cy01 = *(const float4*)(cyp + n);
        float4 cy23 = *(const float4*)(cyp + n + 2);
        float4 sx4  = *(const float4*)(sxp + n);
        float4 sy4  = *(const float4*)(syp + n);
        float4 C4   = *(const float4*)(Cp + n);

        float  sv[4];
        float2 ev[4];
        sv[0] = sx4.x + sy4.x; sv[1] = sx4.y + sy4.y;
        sv[2] = sx4.z + sy4.z; sv[3] = sx4.w + sy4.w;
        ev[0] = make_float2(cx01.x * cy01.x - cx01.y * cy01.y,
                            cx01.x * cy01.y + cx01.y * cy01.x);
        ev[1] = make_float2(cx01.z * cy01.z - cx01.w * cy01.w,
                            cx01.z * cy01.w + cx01.w * cy01.z);
        ev[2] = make_float2(cx23.x * cy23.x - cx23.y * cy23.y,
                            cx23.x * cy23.y + cx23.y * cy23.x);
        ev[3] = make_float2(cx23.z * cy23.z - cx23.w * cy23.w,
                            cx23.z * cy23.w + cx23.w * cy23.z);

        // 4 edges: (prev->v0), (v0->v1), (v1->v2), (v2->v3)
        float sa[4], sb[4];
        float2 ea[4], eb[4];
        sa[0] = sp;    ea[0] = ep;    sb[0] = sv[0]; eb[0] = ev[0];
        sa[1] = sv[0]; ea[1] = ev[0]; sb[1] = sv[1]; eb[1] = ev[1];
        sa[2] = sv[1]; ea[2] = ev[1]; sb[2] = sv[2]; eb[2] = ev[2];
        sa[3] = sv[2]; ea[3] = ev[2]; sb[3] = sv[3]; eb[3] = ev[3];
        float Ce[4] = { Cprev, C4.x, C4.y, C4.z };

        float d[4], nr[4], ni[4];
        #pragma unroll
        for (int j = 0; j < 4; j++) {
            float dab = sa[j] - sb[j];
            d[j]  = dab * sa[j] * sb[j];
            float tr = ea[j].x * sb[j];
            tr = fmaf(-eb[j].x, sa[j], tr);
            nr[j] = tr + dab;
            float ti = ea[j].y * sb[j];
            ni[j] = fmaf(-eb[j].y, sa[j], ti);
        }

        // Montgomery batch inversion: 1 RCP for 4 denominators
        float p01  = d[0] * d[1];
        float p012 = p01 * d[2];
        float p    = p012 * d[3];
        if (fabsf(p) > 1e-30f) {
            float r   = frcp(p);
            float i3  = r * p012;
            float t2  = r * d[3];
            float i2  = t2 * p01;
            float t1  = t2 * d[2];
            float i1  = t1 * d[0];
            float i0  = t1 * d[1];
            float w0 = Ce[0] * i0, w1 = Ce[1] * i1, w2 = Ce[2] * i2, w3 = Ce[3] * i3;
            accR = fmaf(nr[0], w0, accR); accI = fmaf(ni[0], w0, accI);
            accR = fmaf(nr[1], w1, accR); accI = fmaf(ni[1], w1, accI);
            accR = fmaf(nr[2], w2, accR); accI = fmaf(ni[2], w2, accI);
            accR = fmaf(nr[3], w3, accR); accI = fmaf(ni[3], w3, accI);
        } else {
            #pragma unroll
            for (int j = 0; j < 4; j++) {
                float Sr, Si;
                if (d[j] != 0.f) {
                    float r = frcp(d[j]);
                    Sr = nr[j] * r; Si = ni[j] * r;
                } else {
                    slow_S(sa[j], ea[j], sb[j], eb[j], Sr, Si);
                }
                accR = fmaf(Sr, Ce[j], accR);
                accI = fmaf(Si, Ce[j], accI);
            }
        }

        sp = sv[3]; ep = ev[3]; Cprev = C4.w;
    }

    // gamma*SCALE = -2 * (64*64/4) = -2048
    g_feats[b][bin * 2]     = -2048.0f * accR;
    g_feats[b][bin * 2 + 1] = -2048.0f * accI;
}

// ============================================================
// GEMM1 (split-K): p1[s][m][j] = sum_{k in chunk s} feats[m][k] * W1[k][j]
// ============================================================
__global__ __launch_bounds__(256) void gemm1_kernel(const float* __restrict__ W1) {
    __shared__ float sh[KC1 * 32];
    int s = blockIdx.y;
    int j = blockIdx.x * 256 + threadIdx.x;   // 0..1023
    int k0 = s * KC1;

    for (int idx = threadIdx.x; idx < KC1 * 32; idx += 256) {
        int m = idx / KC1, k = idx - m * KC1;
        sh[k * 32 + m] = g_feats[m][k0 + k];
    }
    __syncthreads();

    float acc[32];
    #pragma unroll
    for (int m = 0; m < 32; m++) acc[m] = 0.f;

    const float* wp = W1 + (size_t)k0 * HID + j;
    for (int k = 0; k < KC1; k++) {
        float w = wp[(size_t)k * HID];
        const float4* row = (const float4*)(sh + k * 32);
        #pragma unroll
        for (int q = 0; q < 8; q++) {
            float4 f = row[q];
            acc[4*q+0] = fmaf(f.x, w, acc[4*q+0]);
            acc[4*q+1] = fmaf(f.y, w, acc[4*q+1]);
            acc[4*q+2] = fmaf(f.z, w, acc[4*q+2]);
            acc[4*q+3] = fmaf(f.w, w, acc[4*q+3]);
        }
    }
    #pragma unroll
    for (int m = 0; m < 32; m++) g_p1[s][m][j] = acc[m];
}

__global__ void epi1_kernel(const float* __restrict__ b1) {
    int t = blockIdx.x * 256 + threadIdx.x;   // 32768
    int m = t >> 10, j = t & 1023;
    float a = b1[j];
    #pragma unroll
    for (int s = 0; s < S1; s++) a += g_p1[s][m][j];
    g_h[m][j] = fmaxf(a, 0.f);
}

// ============================================================
// GEMM2 (split-K) + epilogue -> d_out
// ============================================================
__global__ __launch_bounds__(256) void gemm2_kernel(const float* __restrict__ W2) {
    __shared__ float sh[KC2 * 32];
    int s = blockIdx.y;
    int j = blockIdx.x * 256 + threadIdx.x;   // 0..511
    int k0 = s * KC2;

    for (int idx = threadIdx.x; idx < KC2 * 32; idx += 256) {
        int m = idx / KC2, k = idx - m * KC2;
        sh[k * 32 + m] = g_h[m][k0 + k];
    }
    __syncthreads();

    float acc[32];
    #pragma unroll
    for (int m = 0; m < 32; m++) acc[m] = 0.f;

    const float* wp = W2 + (size_t)k0 * OUTD + j;
    for (int k = 0; k < KC2; k++) {
        float w = wp[(size_t)k * OUTD];
        const float4* row = (const float4*)(sh + k * 32);
        #pragma unroll
        for (int q = 0; q < 8; q++) {
            float4 f = row[q];
            acc[4*q+0] = fmaf(f.x, w, acc[4*q+0]);
            acc[4*q+1] = fmaf(f.y, w, acc[4*q+1]);
            acc[4*q+2] = fmaf(f.z, w, acc[4*q+2]);
            acc[4*q+3] = fmaf(f.w, w, acc[4*q+3]);
        }
    }
    #pragma unroll
    for (int m = 0; m < 32; m++) g_p2[s][m][j] = acc[m];
}

__global__ void epi2_kernel(const float* __restrict__ b2, float* __restrict__ out) {
    int t = blockIdx.x * 256 + threadIdx.x;   // 16384 = m*512 + j
    int j = t & 511;
    float a = b2[j];
    int m = t >> 9;
    #pragma unroll
    for (int s = 0; s < S2; s++) a += g_p2[s][m][j];
    out[t] = a;
}

// ============================================================
extern "C" void kernel_launch(void* const* d_in, const int* in_sizes, int n_in,
                              void* d_out, int out_size) {
    const float* P  = (const float*)d_in[0];
    const float* W1 = (const float*)d_in[1];
    const float* b1 = (const float*)d_in[2];
    const float* W2 = (const float*)d_in[3];
    const float* b2 = (const float*)d_in[4];
    float* out = (float*)d_out;

    pass1_kernel<<<(NB * NV + 255) / 256, 256>>>(P);
    pass2_kernel<<<(NB * NBINS) / 128, 128>>>();            // 528 blocks, exact
    gemm1_kernel<<<dim3(HID / 256, S1), 256>>>(W1);
    epi1_kernel<<<(NB * HID) / 256, 256>>>(b1);
    gemm2_kernel<<<dim3(OUTD / 256, S2), 256>>>(W2);
    epi2_kernel<<<(NB * OUTD) / 256, 256>>>(b2, out);
}

// round 2
// speedup vs baseline: 1.3455x; 1.3455x over previous
#include <cuda_runtime.h>
#include <math.h>

#define NB      32          // batch
#define NV      256         // vertices per polygon
#define FX      64
#define FYH     33          // FY/2+1
#define NBINS   (FX*FYH)    // 2112
#define NUFT_DIM (NBINS*2)  // 4224
#define HID     1024
#define OUTD    512

#define S1      32          // split-K for GEMM1
#define KC1     (NUFT_DIM/S1)   // 132
#define S2      16
#define KC2     (HID/S2)        // 64

// -------- device scratch (no allocations allowed) --------
// edge-major layout: for a fixed edge n, k-entries are contiguous -> coalesced
__device__ float2 g_cx[NB][NV][FX];     // e^{-i pi kx vx}
__device__ float2 g_cy[NB][NV][FYH];    // e^{-i pi ky vy}
__device__ float4 g_pvc[NB][NV];        // (pi*vx, pi*vy, -2048*C, 0)
__device__ float  g_feats[NB][NUFT_DIM];
__device__ float  g_h[NB][HID];
__device__ float  g_p1[S1][NB][HID];
__device__ float  g_p2[S2][NB][OUTD];

__device__ __forceinline__ float frcp(float x) {
    float r; asm("rcp.approx.ftz.f32 %0, %1;" : "=f"(r) : "f"(x)); return r;
}

// ============================================================
// Pass 1: one thread per table entry. t -> (b, n, k), k in [0,97)
//   k <  64 : cx entry for kx index k
//   k >= 64 : cy entry for ky index k-64; k==96 also writes pvc
// ============================================================
__global__ __launch_bounds__(256) void pass1_kernel(const float* __restrict__ P) {
    int t = blockIdx.x * 256 + threadIdx.x;
    if (t >= NB * NV * 97) return;
    int bn = t / 97;
    int k  = t - bn * 97;
    int b = bn >> 8, n = bn & 255;
    const float PI = 3.14159265358979323846f;

    float vx = P[bn * 2], vy = P[bn * 2 + 1];

    if (k < 64) {
        int kk = (k < 32) ? k : k - 64;
        float s = (PI * (float)kk) * vx;
        float sn, cs; sincosf(s, &sn, &cs);
        g_cx[b][n][k] = make_float2(cs, -sn);
    } else {
        int y = k - 64;
        float s = (PI * (float)y) * vy;
        float sn, cs; sincosf(s, &sn, &cs);
        g_cy[b][n][y] = make_float2(cs, -sn);
        if (y == 32) {
            int n1 = (n + 1) & 255;
            float wx = P[(b * NV + n1) * 2], wy = P[(b * NV + n1) * 2 + 1];
            float C = 0.5f * (vx * wy - vy * wx);
            g_pvc[b][n] = make_float4(PI * vx, PI * vy, -2048.0f * C, 0.0f);
        }
    }
}

// exact reference semantics when a denominator is 0 (rare path)
__device__ __noinline__ void slow_S(float sa, float2 ea, float sb, float2 eb,
                                    float& Sr, float& Si) {
    float dab = sa - sb;
    float den1 = dab * sa;
    float den2 = -dab * sb;
    float den3 = sa * sb;
    Sr = 0.f; Si = 0.f;
    if (den1 != 0.f) { float r = frcp(den1); Sr += ea.x * r; Si += ea.y * r; }
    if (den2 != 0.f) { float r = frcp(den2); Sr += eb.x * r; Si += eb.y * r; }
    if (den3 != 0.f) { float r = frcp(den3); Sr += r; }
}

// ============================================================
// Pass 2: NUFT spectrum -> feats
// block = (33 y, 4 x), grid = (16 x-tiles, 32 b)
// lanes within a warp span consecutive y -> cy loads coalesced,
// cx / pvc broadcast.
// ============================================================
__global__ __launch_bounds__(132) void pass2_kernel() {
    int y = threadIdx.x;                       // 0..32
    int x = blockIdx.x * 4 + threadIdx.y;      // 0..63
    int b = blockIdx.y;

    float kxf = (float)((x < 32) ? x : x - 64);
    float kyf = (float)y;

    const float2* __restrict__ cxb = &g_cx[b][0][x];   // stride FX float2
    const float2* __restrict__ cyb = &g_cy[b][0][y];   // stride FYH float2
    const float4* __restrict__ pvb = g_pvc[b];

    // carry = vertex NV-1 (edge 255 is 255 -> 0)
    float4 pvp = pvb[NV - 1];
    float  sp  = fmaf(kxf, pvp.x, kyf * pvp.y);
    float2 a   = cxb[(NV - 1) * FX];
    float2 bb  = cyb[(NV - 1) * FYH];
    float2 ep  = make_float2(a.x * bb.x - a.y * bb.y, a.x * bb.y + a.y * bb.x);
    float  Cprev = pvp.z;

    float accR = 0.f, accI = 0.f;

    #pragma unroll 2
    for (int g = 0; g < NV / 4; g++) {
        int n = 4 * g;

        float  sv[4], Cv[4];
        float2 ev[4];
        #pragma unroll
        for (int j = 0; j < 4; j++) {
            float4 pv = pvb[n + j];
            sv[j] = fmaf(kxf, pv.x, kyf * pv.y);
            Cv[j] = pv.z;
            float2 cx = cxb[(n + j) * FX];
            float2 cy = cyb[(n + j) * FYH];
            ev[j] = make_float2(fmaf(cx.x, cy.x, -cx.y * cy.y),
                                fmaf(cx.x, cy.y,  cx.y * cy.x));
        }

        // 4 edges: (prev->v0), (v0->v1), (v1->v2), (v2->v3)
        float sa[4], sb[4];
        float2 ea[4], eb[4];
        sa[0] = sp;    ea[0] = ep;    sb[0] = sv[0]; eb[0] = ev[0];
        sa[1] = sv[0]; ea[1] = ev[0]; sb[1] = sv[1]; eb[1] = ev[1];
        sa[2] = sv[1]; ea[2] = ev[1]; sb[2] = sv[2]; eb[2] = ev[2];
        sa[3] = sv[2]; ea[3] = ev[2]; sb[3] = sv[3]; eb[3] = ev[3];
        float Ce[4] = { Cprev, Cv[0], Cv[1], Cv[2] };

        float d[4], nr[4], ni[4];
        #pragma unroll
        for (int j = 0; j < 4; j++) {
            float dab = sa[j] - sb[j];
            d[j]  = dab * sa[j] * sb[j];
            float tr = ea[j].x * sb[j];
            tr = fmaf(-eb[j].x, sa[j], tr);
            nr[j] = tr + dab;
            float ti = ea[j].y * sb[j];
            ni[j] = fmaf(-eb[j].y, sa[j], ti);
        }

        // Montgomery batch inversion: 1 RCP for 4 denominators
        float p01  = d[0] * d[1];
        float p012 = p01 * d[2];
        float p    = p012 * d[3];
        if (fabsf(p) > 1e-30f) {
            float r   = frcp(p);
            float i3  = r * p012;
            float t2  = r * d[3];
            float i2  = t2 * p01;
            float t1  = t2 * d[2];
            float i1  = t1 * d[0];
            float i0  = t1 * d[1];
            float w0 = Ce[0] * i0, w1 = Ce[1] * i1, w2 = Ce[2] * i2, w3 = Ce[3] * i3;
            accR = fmaf(nr[0], w0, accR); accI = fmaf(ni[0], w0, accI);
            accR = fmaf(nr[1], w1, accR); accI = fmaf(ni[1], w1, accI);
            accR = fmaf(nr[2], w2, accR); accI = fmaf(ni[2], w2, accI);
            accR = fmaf(nr[3], w3, accR); accI = fmaf(ni[3], w3, accI);
        } else {
            #pragma unroll
            for (int j = 0; j < 4; j++) {
                float Sr, Si;
                if (d[j] != 0.f) {
                    float r = frcp(d[j]);
                    Sr = nr[j] * r; Si = ni[j] * r;
                } else {
                    slow_S(sa[j], ea[j], sb[j], eb[j], Sr, Si);
                }
                accR = fmaf(Sr, Ce[j], accR);
                accI = fmaf(Si, Ce[j], accI);
            }
        }

        sp = sv[3]; ep = ev[3]; Cprev = Cv[3];
    }

    int bin = x * FYH + y;
    g_feats[b][bin * 2]     = accR;   // scale already folded into C
    g_feats[b][bin * 2 + 1] = accI;
}

// ============================================================
// GEMM1 (split-K): p1[s][m][j] = sum_{k in chunk s} feats[m][k] * W1[k][j]
// ============================================================
__global__ __launch_bounds__(256) void gemm1_kernel(const float* __restrict__ W1) {
    __shared__ float sh[KC1 * 32];
    int s = blockIdx.y;
    int j = blockIdx.x * 256 + threadIdx.x;   // 0..1023
    int k0 = s * KC1;

    for (int idx = threadIdx.x; idx < KC1 * 32; idx += 256) {
        int m = idx / KC1, k = idx - m * KC1;
        sh[k * 32 + m] = g_feats[m][k0 + k];
    }
    __syncthreads();

    float acc[32];
    #pragma unroll
    for (int m = 0; m < 32; m++) acc[m] = 0.f;

    const float* wp = W1 + (size_t)k0 * HID + j;
    #pragma unroll 4
    for (int k = 0; k < KC1; k++) {
        float w = wp[(size_t)k * HID];
        const float4* row = (const float4*)(sh + k * 32);
        #pragma unroll
        for (int q = 0; q < 8; q++) {
            float4 f = row[q];
            acc[4*q+0] = fmaf(f.x, w, acc[4*q+0]);
            acc[4*q+1] = fmaf(f.y, w, acc[4*q+1]);
            acc[4*q+2] = fmaf(f.z, w, acc[4*q+2]);
            acc[4*q+3] = fmaf(f.w, w, acc[4*q+3]);
        }
    }
    #pragma unroll
    for (int m = 0; m < 32; m++) g_p1[s][m][j] = acc[m];
}

// epilogue 1: float4 across j, 32 independent LDG.128 per thread
__global__ __launch_bounds__(128) void epi1_kernel(const float* __restrict__ b1) {
    int t = blockIdx.x * 128 + threadIdx.x;   // 8192 = m*256 + jq
    int m = t >> 8, jq = t & 255;
    const float4* bp = (const float4*)b1 + jq;
    float4 a = *bp;
    #pragma unroll
    for (int s = 0; s < S1; s++) {
        float4 p = *((const float4*)(&g_p1[s][m][0]) + jq);
        a.x += p.x; a.y += p.y; a.z += p.z; a.w += p.w;
    }
    a.x = fmaxf(a.x, 0.f); a.y = fmaxf(a.y, 0.f);
    a.z = fmaxf(a.z, 0.f); a.w = fmaxf(a.w, 0.f);
    *((float4*)(&g_h[m][0]) + jq) = a;
}

// ============================================================
// GEMM2 (split-K)
// ============================================================
__global__ __launch_bounds__(256) void gemm2_kernel(const float* __restrict__ W2) {
    __shared__ float sh[KC2 * 32];
    int s = blockIdx.y;
    int j = blockIdx.x * 256 + threadIdx.x;   // 0..511
    int k0 = s * KC2;

    for (int idx = threadIdx.x; idx < KC2 * 32; idx += 256) {
        int m = idx / KC2, k = idx - m * KC2;
        sh[k * 32 + m] = g_h[m][k0 + k];
    }
    __syncthreads();

    float acc[32];
    #pragma unroll
    for (int m = 0; m < 32; m++) acc[m] = 0.f;

    const float* wp = W2 + (size_t)k0 * OUTD + j;
    #pragma unroll 4
    for (int k = 0; k < KC2; k++) {
        float w = wp[(size_t)k * OUTD];
        const float4* row = (const float4*)(sh + k * 32);
        #pragma unroll
        for (int q = 0; q < 8; q++) {
            float4 f = row[q];
            acc[4*q+0] = fmaf(f.x, w, acc[4*q+0]);
            acc[4*q+1] = fmaf(f.y, w, acc[4*q+1]);
            acc[4*q+2] = fmaf(f.z, w, acc[4*q+2]);
            acc[4*q+3] = fmaf(f.w, w, acc[4*q+3]);
        }
    }
    #pragma unroll
    for (int m = 0; m < 32; m++) g_p2[s][m][j] = acc[m];
}

__global__ __launch_bounds__(128) void epi2_kernel(const float* __restrict__ b2,
                                                   float* __restrict__ out) {
    int t = blockIdx.x * 128 + threadIdx.x;   // 4096 = m*128 + jq
    int m = t >> 7, jq = t & 127;
    float4 a = *((const float4*)b2 + jq);
    #pragma unroll
    for (int s = 0; s < S2; s++) {
        float4 p = *((const float4*)(&g_p2[s][m][0]) + jq);
        a.x += p.x; a.y += p.y; a.z += p.z; a.w += p.w;
    }
    *((float4*)out + t) = a;
}

// ============================================================
extern "C" void kernel_launch(void* const* d_in, const int* in_sizes, int n_in,
                              void* d_out, int out_size) {
    const float* P  = (const float*)d_in[0];
    const float* W1 = (const float*)d_in[1];
    const float* b1 = (const float*)d_in[2];
    const float* W2 = (const float*)d_in[3];
    const float* b2 = (const float*)d_in[4];
    float* out = (float*)d_out;

    pass1_kernel<<<(NB * NV * 97 + 255) / 256, 256>>>(P);
    pass2_kernel<<<dim3(FX / 4, NB), dim3(FYH, 4)>>>();
    gemm1_kernel<<<dim3(HID / 256, S1), 256>>>(W1);
    epi1_kernel<<<NB * HID / 4 / 128, 128>>>(b1);
    gemm2_kernel<<<dim3(OUTD / 256, S2), 256>>>(W2);
    epi2_kernel<<<NB * OUTD / 4 / 128, 128>>>(b2, out);
}

// round 3
// speedup vs baseline: 1.7534x; 1.3032x over previous
#include <cuda_runtime.h>
#include <math.h>

#define NB      32          // batch
#define NV      256         // vertices per polygon
#define FX      64
#define FYH     33          // FY/2+1
#define NBINS   (FX*FYH)    // 2112
#define NUFT_DIM (NBINS*2)  // 4224
#define HID     1024
#define OUTD    512

#define EPARTS  2           // edge-split factor for pass2
#define EPN     (NV/EPARTS) // 128 edges per part

#define S1      32          // split-K for GEMM1
#define KC1     (NUFT_DIM/S1)   // 132
#define S2      16
#define KC2     (HID/S2)        // 64

// -------- device scratch (no allocations allowed) --------
// edge-major layout: for a fixed edge n, k-entries are contiguous -> coalesced
__device__ float2 g_cx[NB][NV][FX];     // e^{-i pi kx vx}
__device__ float2 g_cy[NB][NV][FYH];    // e^{-i pi ky vy}
__device__ float4 g_pvc[NB][NV];        // (pi*vx, pi*vy, -2048*C, 0)
__device__ float  g_feats2[EPARTS][NB][NUFT_DIM];
__device__ float  g_h[NB][HID];
__device__ float  g_p1[S1][NB][HID];
__device__ float  g_p2[S2][NB][OUTD];

__device__ __forceinline__ float frcp(float x) {
    float r; asm("rcp.approx.ftz.f32 %0, %1;" : "=f"(r) : "f"(x)); return r;
}

// ============================================================
// Pass 1: one thread per table entry. t -> (b, n, k), k in [0,97)
// ============================================================
__global__ __launch_bounds__(256) void pass1_kernel(const float* __restrict__ P) {
    int t = blockIdx.x * 256 + threadIdx.x;
    if (t >= NB * NV * 97) return;
    int bn = t / 97;
    int k  = t - bn * 97;
    int b = bn >> 8, n = bn & 255;
    const float PI = 3.14159265358979323846f;

    float vx = P[bn * 2], vy = P[bn * 2 + 1];

    if (k < 64) {
        int kk = (k < 32) ? k : k - 64;
        float s = (PI * (float)kk) * vx;
        float sn, cs; sincosf(s, &sn, &cs);
        g_cx[b][n][k] = make_float2(cs, -sn);
    } else {
        int y = k - 64;
        float s = (PI * (float)y) * vy;
        float sn, cs; sincosf(s, &sn, &cs);
        g_cy[b][n][y] = make_float2(cs, -sn);
        if (y == 32) {
            int n1 = (n + 1) & 255;
            float wx = P[(b * NV + n1) * 2], wy = P[(b * NV + n1) * 2 + 1];
            float C = 0.5f * (vx * wy - vy * wx);
            g_pvc[b][n] = make_float4(PI * vx, PI * vy, -2048.0f * C, 0.0f);
        }
    }
}

// exact reference semantics when a denominator is 0 (rare path)
__device__ __noinline__ void slow_S(float sa, float2 ea, float sb, float2 eb,
                                    float& Sr, float& Si) {
    float dab = sa - sb;
    float den1 = dab * sa;
    float den2 = -dab * sb;
    float den3 = sa * sb;
    Sr = 0.f; Si = 0.f;
    if (den1 != 0.f) { float r = frcp(den1); Sr += ea.x * r; Si += ea.y * r; }
    if (den2 != 0.f) { float r = frcp(den2); Sr += eb.x * r; Si += eb.y * r; }
    if (den3 != 0.f) { float r = frcp(den3); Sr += r; }
}

// ============================================================
// Pass 2: NUFT spectrum -> feats partials (edge-split by blockIdx.z)
// block = (33 y, 4 x), grid = (16 x-tiles, 32 b, EPARTS)
// ============================================================
__global__ __launch_bounds__(132) void pass2_kernel() {
    int y = threadIdx.x;                       // 0..32
    int x = blockIdx.x * 4 + threadIdx.y;      // 0..63
    int b = blockIdx.y;
    int part = blockIdx.z;
    int n0 = part * EPN;                       // first b-vertex of this part

    float kxf = (float)((x < 32) ? x : x - 64);
    float kyf = (float)y;

    const float2* __restrict__ cxb = &g_cx[b][0][x];   // stride FX float2
    const float2* __restrict__ cyb = &g_cy[b][0][y];   // stride FYH float2
    const float4* __restrict__ pvb = g_pvc[b];

    // carry = vertex n0-1 (mod NV): its sigma, exp, C
    int np = (n0 + NV - 1) & (NV - 1);
    float4 pvp = pvb[np];
    float  sp  = fmaf(kxf, pvp.x, kyf * pvp.y);
    float2 a   = cxb[np * FX];
    float2 bb  = cyb[np * FYH];
    float2 ep  = make_float2(a.x * bb.x - a.y * bb.y, a.x * bb.y + a.y * bb.x);
    float  Cprev = pvp.z;

    float accR = 0.f, accI = 0.f;

    #pragma unroll 2
    for (int g = 0; g < EPN / 4; g++) {
        int n = n0 + 4 * g;

        float  sv[4], Cv[4];
        float2 ev[4];
        #pragma unroll
        for (int j = 0; j < 4; j++) {
            float4 pv = pvb[n + j];
            sv[j] = fmaf(kxf, pv.x, kyf * pv.y);
            Cv[j] = pv.z;
            float2 cx = cxb[(n + j) * FX];
            float2 cy = cyb[(n + j) * FYH];
            ev[j] = make_float2(fmaf(cx.x, cy.x, -cx.y * cy.y),
                                fmaf(cx.x, cy.y,  cx.y * cy.x));
        }

        // 4 edges: (prev->v0), (v0->v1), (v1->v2), (v2->v3)
        float sa[4], sb[4];
        float2 ea[4], eb[4];
        sa[0] = sp;    ea[0] = ep;    sb[0] = sv[0]; eb[0] = ev[0];
        sa[1] = sv[0]; ea[1] = ev[0]; sb[1] = sv[1]; eb[1] = ev[1];
        sa[2] = sv[1]; ea[2] = ev[1]; sb[2] = sv[2]; eb[2] = ev[2];
        sa[3] = sv[2]; ea[3] = ev[2]; sb[3] = sv[3]; eb[3] = ev[3];
        float Ce[4] = { Cprev, Cv[0], Cv[1], Cv[2] };

        float d[4], nr[4], ni[4];
        #pragma unroll
        for (int j = 0; j < 4; j++) {
            float dab = sa[j] - sb[j];
            d[j]  = dab * sa[j] * sb[j];
            float tr = ea[j].x * sb[j];
            tr = fmaf(-eb[j].x, sa[j], tr);
            nr[j] = tr + dab;
            float ti = ea[j].y * sb[j];
            ni[j] = fmaf(-eb[j].y, sa[j], ti);
        }

        // Montgomery batch inversion: 1 RCP for 4 denominators
        float p01  = d[0] * d[1];
        float p012 = p01 * d[2];
        float p    = p012 * d[3];
        if (fabsf(p) > 1e-30f) {
            float r   = frcp(p);
            float i3  = r * p012;
            float t2  = r * d[3];
            float i2  = t2 * p01;
            float t1  = t2 * d[2];
            float i1  = t1 * d[0];
            float i0  = t1 * d[1];
            float w0 = Ce[0] * i0, w1 = Ce[1] * i1, w2 = Ce[2] * i2, w3 = Ce[3] * i3;
            accR = fmaf(nr[0], w0, accR); accI = fmaf(ni[0], w0, accI);
            accR = fmaf(nr[1], w1, accR); accI = fmaf(ni[1], w1, accI);
            accR = fmaf(nr[2], w2, accR); accI = fmaf(ni[2], w2, accI);
            accR = fmaf(nr[3], w3, accR); accI = fmaf(ni[3], w3, accI);
        } else {
            #pragma unroll
            for (int j = 0; j < 4; j++) {
                float Sr, Si;
                if (d[j] != 0.f) {
                    float r = frcp(d[j]);
                    Sr = nr[j] * r; Si = ni[j] * r;
                } else {
                    slow_S(sa[j], ea[j], sb[j], eb[j], Sr, Si);
                }
                accR = fmaf(Sr, Ce[j], accR);
                accI = fmaf(Si, Ce[j], accI);
            }
        }

        sp = sv[3]; ep = ev[3]; Cprev = Cv[3];
    }

    int bin = x * FYH + y;
    g_feats2[part][b][bin * 2]     = accR;   // scale folded into C
    g_feats2[part][b][bin * 2 + 1] = accI;
}

// ============================================================
// GEMM1 (split-K): p1[s][m][j] = sum_{k in chunk s} feats[m][k] * W1[k][j]
// smem fill sums the EPARTS partial spectra.
// ============================================================
__global__ __launch_bounds__(256) void gemm1_kernel(const float* __restrict__ W1) {
    __shared__ float sh[KC1 * 32];
    int s = blockIdx.y;
    int j = blockIdx.x * 256 + threadIdx.x;   // 0..1023
    int k0 = s * KC1;

    for (int idx = threadIdx.x; idx < KC1 * 32; idx += 256) {
        int m = idx / KC1, k = idx - m * KC1;
        sh[k * 32 + m] = g_feats2[0][m][k0 + k] + g_feats2[1][m][k0 + k];
    }
    __syncthreads();

    float acc[32];
    #pragma unroll
    for (int m = 0; m < 32; m++) acc[m] = 0.f;

    const float* wp = W1 + (size_t)k0 * HID + j;
    #pragma unroll 4
    for (int k = 0; k < KC1; k++) {
        float w = wp[(size_t)k * HID];
        const float4* row = (const float4*)(sh + k * 32);
        #pragma unroll
        for (int q = 0; q < 8; q++) {
            float4 f = row[q];
            acc[4*q+0] = fmaf(f.x, w, acc[4*q+0]);
            acc[4*q+1] = fmaf(f.y, w, acc[4*q+1]);
            acc[4*q+2] = fmaf(f.z, w, acc[4*q+2]);
            acc[4*q+3] = fmaf(f.w, w, acc[4*q+3]);
        }
    }
    #pragma unroll
    for (int m = 0; m < 32; m++) g_p1[s][m][j] = acc[m];
}

// epilogue 1: scalar thread per (m, j) -> 32768 threads, 32 indep coalesced loads
__global__ __launch_bounds__(256) void epi1_kernel(const float* __restrict__ b1) {
    int t = blockIdx.x * 256 + threadIdx.x;   // 32768 = m*1024 + j
    int m = t >> 10, j = t & 1023;
    float a = b1[j];
    #pragma unroll
    for (int s = 0; s < S1; s++) a += g_p1[s][m][j];
    g_h[m][j] = fmaxf(a, 0.f);
}

// ============================================================
// GEMM2 (split-K)
// ============================================================
__global__ __launch_bounds__(256) void gemm2_kernel(const float* __restrict__ W2) {
    __shared__ float sh[KC2 * 32];
    int s = blockIdx.y;
    int j = blockIdx.x * 256 + threadIdx.x;   // 0..511
    int k0 = s * KC2;

    for (int idx = threadIdx.x; idx < KC2 * 32; idx += 256) {
        int m = idx / KC2, k = idx - m * KC2;
        sh[k * 32 + m] = g_h[m][k0 + k];
    }
    __syncthreads();

    float acc[32];
    #pragma unroll
    for (int m = 0; m < 32; m++) acc[m] = 0.f;

    const float* wp = W2 + (size_t)k0 * OUTD + j;
    #pragma unroll 4
    for (int k = 0; k < KC2; k++) {
        float w = wp[(size_t)k * OUTD];
        const float4* row = (const float4*)(sh + k * 32);
        #pragma unroll
        for (int q = 0; q < 8; q++) {
            float4 f = row[q];
            acc[4*q+0] = fmaf(f.x, w, acc[4*q+0]);
            acc[4*q+1] = fmaf(f.y, w, acc[4*q+1]);
            acc[4*q+2] = fmaf(f.z, w, acc[4*q+2]);
            acc[4*q+3] = fmaf(f.w, w, acc[4*q+3]);
        }
    }
    #pragma unroll
    for (int m = 0; m < 32; m++) g_p2[s][m][j] = acc[m];
}

// epilogue 2: scalar thread per (m, j) -> 16384 threads
__global__ __launch_bounds__(256) void epi2_kernel(const float* __restrict__ b2,
                                                   float* __restrict__ out) {
    int t = blockIdx.x * 256 + threadIdx.x;   // 16384 = m*512 + j
    int j = t & 511;
    int m = t >> 9;
    float a = b2[j];
    #pragma unroll
    for (int s = 0; s < S2; s++) a += g_p2[s][m][j];
    out[t] = a;
}

// ============================================================
extern "C" void kernel_launch(void* const* d_in, const int* in_sizes, int n_in,
                              void* d_out, int out_size) {
    const float* P  = (const float*)d_in[0];
    const float* W1 = (const float*)d_in[1];
    const float* b1 = (const float*)d_in[2];
    const float* W2 = (const float*)d_in[3];
    const float* b2 = (const float*)d_in[4];
    float* out = (float*)d_out;

    pass1_kernel<<<(NB * NV * 97 + 255) / 256, 256>>>(P);
    pass2_kernel<<<dim3(FX / 4, NB, EPARTS), dim3(FYH, 4)>>>();
    gemm1_kernel<<<dim3(HID / 256, S1), 256>>>(W1);
    epi1_kernel<<<NB * HID / 256, 256>>>(b1);
    gemm2_kernel<<<dim3(OUTD / 256, S2), 256>>>(W2);
    epi2_kernel<<<NB * OUTD / 256, 256>>>(b2, out);
}

// round 5
// speedup vs baseline: 1.7705x; 1.0097x over previous
#include <cuda_runtime.h>
#include <math.h>

#define NB      32          // batch
#define NV      256         // vertices per polygon
#define FX      64
#define FYH     33          // FY/2+1
#define NBINS   (FX*FYH)    // 2112
#define NUFT_DIM (NBINS*2)  // 4224
#define HID     1024
#define OUTD    512

#define EPARTS  4           // edge-split factor for pass2
#define EPN     (NV/EPARTS) // 64 edges per part

#define S1      16          // split-K for GEMM1
#define KC1     (NUFT_DIM/S1)   // 264
#define S2      16
#define KC2     (HID/S2)        // 64

// -------- device scratch (no allocations allowed) --------
__device__ float2 g_cx[NB][NV][FX];     // e^{-i pi kx vx}
__device__ float2 g_cy[NB][NV][FYH];    // e^{-i pi ky vy}
__device__ float4 g_pvc[NB][NV];        // (pi*vx, pi*vy, -2048*C, 0)
__device__ float  g_f2T[EPARTS][NUFT_DIM][NB];   // partial spectra, transposed
__device__ float  g_featT[NUFT_DIM][NB];         // summed, transposed (k-major)
__device__ float  g_hT[HID][NB];                 // hidden, transposed (j-major)
__device__ float  g_p1[S1][NB][HID];
__device__ float  g_p2[S2][NB][OUTD];

__device__ __forceinline__ float frcp(float x) {
    float r; asm("rcp.approx.ftz.f32 %0, %1;" : "=f"(r) : "f"(x)); return r;
}
__device__ __forceinline__ unsigned long long pack2(float w) {
    unsigned int u = __float_as_uint(w);
    unsigned long long d;
    asm("mov.b64 %0, {%1, %1};" : "=l"(d) : "r"(u));
    return d;
}
#define FMA2(d, a, b) asm("fma.rn.f32x2 %0, %1, %2, %0;" : "+l"(d) : "l"(a), "l"(b))
__device__ __forceinline__ void unpack2(unsigned long long d, float& lo, float& hi) {
    unsigned int a, b;
    asm("mov.b64 {%0, %1}, %2;" : "=r"(a), "=r"(b) : "l"(d));
    lo = __uint_as_float(a); hi = __uint_as_float(b);
}

// ============================================================
// Pass 1: one thread per table entry. t -> (b, n, k), k in [0,97)
// ============================================================
__global__ __launch_bounds__(256) void pass1_kernel(const float* __restrict__ P) {
    int t = blockIdx.x * 256 + threadIdx.x;
    if (t >= NB * NV * 97) return;
    int bn = t / 97;
    int k  = t - bn * 97;
    int b = bn >> 8, n = bn & 255;
    const float PI = 3.14159265358979323846f;

    float vx = P[bn * 2], vy = P[bn * 2 + 1];

    if (k < 64) {
        int kk = (k < 32) ? k : k - 64;
        float s = (PI * (float)kk) * vx;
        float sn, cs; sincosf(s, &sn, &cs);
        g_cx[b][n][k] = make_float2(cs, -sn);
    } else {
        int y = k - 64;
        float s = (PI * (float)y) * vy;
        float sn, cs; sincosf(s, &sn, &cs);
        g_cy[b][n][y] = make_float2(cs, -sn);
        if (y == 32) {
            int n1 = (n + 1) & 255;
            float wx = P[(b * NV + n1) * 2], wy = P[(b * NV + n1) * 2 + 1];
            float C = 0.5f * (vx * wy - vy * wx);
            g_pvc[b][n] = make_float4(PI * vx, PI * vy, -2048.0f * C, 0.0f);
        }
    }
}

// exact reference semantics when a denominator is 0 (rare path)
__device__ __noinline__ void slow_S(float sa, float2 ea, float sb, float2 eb,
                                    float& Sr, float& Si) {
    float dab = sa - sb;
    float den1 = dab * sa;
    float den2 = -dab * sb;
    float den3 = sa * sb;
    Sr = 0.f; Si = 0.f;
    if (den1 != 0.f) { float r = frcp(den1); Sr += ea.x * r; Si += ea.y * r; }
    if (den2 != 0.f) { float r = frcp(den2); Sr += eb.x * r; Si += eb.y * r; }
    if (den3 != 0.f) { float r = frcp(den3); Sr += r; }
}

// ============================================================
// Pass 2: NUFT spectrum -> transposed partial feats
// block = 96 threads over linear bins, grid = (22, NB, EPARTS)
// ============================================================
__global__ __launch_bounds__(96) void pass2_kernel() {
    int bin = blockIdx.x * 96 + threadIdx.x;   // 0..2111
    int x = bin / FYH;
    int y = bin - x * FYH;
    int b = blockIdx.y;
    int part = blockIdx.z;
    int n0 = part * EPN;

    float kxf = (float)((x < 32) ? x : x - 64);
    float kyf = (float)y;

    const float2* __restrict__ cxb = &g_cx[b][0][x];   // stride FX float2
    const float2* __restrict__ cyb = &g_cy[b][0][y];   // stride FYH float2
    const float4* __restrict__ pvb = g_pvc[b];

    // carry = vertex n0-1 (mod NV)
    int np = (n0 + NV - 1) & (NV - 1);
    float4 pvp = pvb[np];
    float  sp  = fmaf(kxf, pvp.x, kyf * pvp.y);
    float2 a   = cxb[np * FX];
    float2 bb  = cyb[np * FYH];
    float2 ep  = make_float2(a.x * bb.x - a.y * bb.y, a.x * bb.y + a.y * bb.x);
    float  Cprev = pvp.z;

    float accR = 0.f, accI = 0.f;

    #pragma unroll 2
    for (int g = 0; g < EPN / 4; g++) {
        int n = n0 + 4 * g;

        float  sv[4], Cv[4];
        float2 ev[4];
        #pragma unroll
        for (int j = 0; j < 4; j++) {
            float4 pv = pvb[n + j];
            sv[j] = fmaf(kxf, pv.x, kyf * pv.y);
            Cv[j] = pv.z;
            float2 cx = cxb[(n + j) * FX];
            float2 cy = cyb[(n + j) * FYH];
            ev[j] = make_float2(fmaf(cx.x, cy.x, -cx.y * cy.y),
                                fmaf(cx.x, cy.y,  cx.y * cy.x));
        }

        float sa[4], sb[4];
        float2 ea[4], eb[4];
        sa[0] = sp;    ea[0] = ep;    sb[0] = sv[0]; eb[0] = ev[0];
        sa[1] = sv[0]; ea[1] = ev[0]; sb[1] = sv[1]; eb[1] = ev[1];
        sa[2] = sv[1]; ea[2] = ev[1]; sb[2] = sv[2]; eb[2] = ev[2];
        sa[3] = sv[2]; ea[3] = ev[2]; sb[3] = sv[3]; eb[3] = ev[3];
        float Ce[4] = { Cprev, Cv[0], Cv[1], Cv[2] };

        float d[4], nr[4], ni[4];
        #pragma unroll
        for (int j = 0; j < 4; j++) {
            float dab = sa[j] - sb[j];
            d[j]  = dab * sa[j] * sb[j];
            float tr = ea[j].x * sb[j];
            tr = fmaf(-eb[j].x, sa[j], tr);
            nr[j] = tr + dab;
            float ti = ea[j].y * sb[j];
            ni[j] = fmaf(-eb[j].y, sa[j], ti);
        }

        // Montgomery batch inversion: 1 RCP for 4 denominators
        float p01  = d[0] * d[1];
        float p012 = p01 * d[2];
        float p    = p012 * d[3];
        if (fabsf(p) > 1e-30f) {
            float r   = frcp(p);
            float i3  = r * p012;
            float t2  = r * d[3];
            float i2  = t2 * p01;
            float t1  = t2 * d[2];
            float i1  = t1 * d[0];
            float i0  = t1 * d[1];
            float w0 = Ce[0] * i0, w1 = Ce[1] * i1, w2 = Ce[2] * i2, w3 = Ce[3] * i3;
            accR = fmaf(nr[0], w0, accR); accI = fmaf(ni[0], w0, accI);
            accR = fmaf(nr[1], w1, accR); accI = fmaf(ni[1], w1, accI);
            accR = fmaf(nr[2], w2, accR); accI = fmaf(ni[2], w2, accI);
            accR = fmaf(nr[3], w3, accR); accI = fmaf(ni[3], w3, accI);
        } else {
            #pragma unroll
            for (int j = 0; j < 4; j++) {
                float Sr, Si;
                if (d[j] != 0.f) {
                    float r = frcp(d[j]);
                    Sr = nr[j] * r; Si = ni[j] * r;
                } else {
                    slow_S(sa[j], ea[j], sb[j], eb[j], Sr, Si);
                }
                accR = fmaf(Sr, Ce[j], accR);
                accI = fmaf(Si, Ce[j], accI);
            }
        }

        sp = sv[3]; ep = ev[3]; Cprev = Cv[3];
    }

    g_f2T[part][bin * 2][b]     = accR;   // scale folded into C
    g_f2T[part][bin * 2 + 1][b] = accI;
}

// ============================================================
// Sum partials: featT[k][m] = sum_p f2T[p][k][m]   (fully coalesced)
// ============================================================
__global__ __launch_bounds__(256) void sumfeat_kernel() {
    int t = blockIdx.x * 256 + threadIdx.x;   // 0 .. NUFT_DIM*NB-1
    const float* f0 = &g_f2T[0][0][0];
    float a = f0[t] + f0[t + NUFT_DIM * NB] + f0[t + 2 * NUFT_DIM * NB]
            + f0[t + 3 * NUFT_DIM * NB];
    (&g_featT[0][0])[t] = a;
}

// ============================================================
// GEMM1 (split-K, FFMA2): p1[s][m][j] = sum_k featT[k][m] * W1[k][j]
// grid (HID/128, S1), block 128
// ============================================================
__global__ __launch_bounds__(128) void gemm1_kernel(const float* __restrict__ W1) {
    __shared__ float sh[KC1 * 32];
    int s = blockIdx.y;
    int j = blockIdx.x * 128 + threadIdx.x;
    int k0 = s * KC1;

    const float* src = &g_featT[k0][0];       // linear: k*32+m
    for (int idx = threadIdx.x; idx < KC1 * 32; idx += 128)
        sh[idx] = src[idx];
    __syncthreads();

    unsigned long long acc2[16];
    #pragma unroll
    for (int q = 0; q < 16; q++) acc2[q] = 0ull;

    const float* wp = W1 + (size_t)k0 * HID + j;
    #pragma unroll 4
    for (int k = 0; k < KC1; k++) {
        unsigned long long w2 = pack2(wp[(size_t)k * HID]);
        const unsigned long long* row = (const unsigned long long*)(sh + k * 32);
        #pragma unroll
        for (int q = 0; q < 16; q++) FMA2(acc2[q], row[q], w2);
    }
    #pragma unroll
    for (int q = 0; q < 16; q++) {
        float lo, hi; unpack2(acc2[q], lo, hi);
        g_p1[s][2 * q][j]     = lo;
        g_p1[s][2 * q + 1][j] = hi;
    }
}

// epilogue 1: float2, 16384 threads; writes transposed hT[j][m]
__global__ __launch_bounds__(128) void epi1_kernel(const float* __restrict__ b1) {
    int t = blockIdx.x * 128 + threadIdx.x;   // 16384 = m*512 + j2
    int m = t >> 9, j2 = t & 511;
    int j = 2 * j2;
    float2 a = *(const float2*)(b1 + j);
    #pragma unroll
    for (int s = 0; s < S1; s++) {
        float2 p = *(const float2*)(&g_p1[s][m][j]);
        a.x += p.x; a.y += p.y;
    }
    g_hT[j][m]     = fmaxf(a.x, 0.f);
    g_hT[j + 1][m] = fmaxf(a.y, 0.f);
}

// ============================================================
// GEMM2 (split-K, FFMA2): grid (OUTD/128, S2), block 128
// ============================================================
__global__ __launch_bounds__(128) void gemm2_kernel(const float* __restrict__ W2) {
    __shared__ float sh[KC2 * 32];
    int s = blockIdx.y;
    int j = blockIdx.x * 128 + threadIdx.x;
    int k0 = s * KC2;

    const float* src = &g_hT[k0][0];
    for (int idx = threadIdx.x; idx < KC2 * 32; idx += 128)
        sh[idx] = src[idx];
    __syncthreads();

    unsigned long long acc2[16];
    #pragma unroll
    for (int q = 0; q < 16; q++) acc2[q] = 0ull;

    const float* wp = W2 + (size_t)k0 * OUTD + j;
    #pragma unroll 8
    for (int k = 0; k < KC2; k++) {
        unsigned long long w2 = pack2(wp[(size_t)k * OUTD]);
        const unsigned long long* row = (const unsigned long long*)(sh + k * 32);
        #pragma unroll
        for (int q = 0; q < 16; q++) FMA2(acc2[q], row[q], w2);
    }
    #pragma unroll
    for (int q = 0; q < 16; q++) {
        float lo, hi; unpack2(acc2[q], lo, hi);
        g_p2[s][2 * q][j]     = lo;
        g_p2[s][2 * q + 1][j] = hi;
    }
}

// epilogue 2: float2, 8192 threads
__global__ __launch_bounds__(128) void epi2_kernel(const float* __restrict__ b2,
                                                   float* __restrict__ out) {
    int t = blockIdx.x * 128 + threadIdx.x;   // 8192 = m*256 + j2
    int m = t >> 8, j2 = t & 255;
    int j = 2 * j2;
    float2 a = *(const float2*)(b2 + j);
    #pragma unroll
    for (int s = 0; s < S2; s++) {
        float2 p = *(const float2*)(&g_p2[s][m][j]);
        a.x += p.x; a.y += p.y;
    }
    *(float2*)(out + m * OUTD + j) = a;
}

// ============================================================
extern "C" void kernel_launch(void* const* d_in, const int* in_sizes, int n_in,
                              void* d_out, int out_size) {
    const float* P  = (const float*)d_in[0];
    const float* W1 = (const float*)d_in[1];
    const float* b1 = (const float*)d_in[2];
    const float* W2 = (const float*)d_in[3];
    const float* b2 = (const float*)d_in[4];
    float* out = (float*)d_out;

    pass1_kernel<<<(NB * NV * 97 + 255) / 256, 256>>>(P);
    pass2_kernel<<<dim3(NBINS / 96, NB, EPARTS), 96>>>();
    sumfeat_kernel<<<NUFT_DIM * NB / 256, 256>>>();
    gemm1_kernel<<<dim3(HID / 128, S1), 128>>>(W1);
    epi1_kernel<<<NB * HID / 2 / 128, 128>>>(b1);
    gemm2_kernel<<<dim3(OUTD / 128, S2), 128>>>(W2);
    epi2_kernel<<<NB * OUTD / 2 / 128, 128>>>(b2, out);
}

// round 6
// speedup vs baseline: 2.0449x; 1.1550x over previous
#include <cuda_runtime.h>
#include <math.h>

#define NB      32          // batch
#define NV      256         // vertices per polygon
#define FX      64
#define FYH     33          // FY/2+1
#define NBINS   (FX*FYH)    // 2112
#define NUFT_DIM (NBINS*2)  // 4224
#define HID     1024
#define OUTD    512

#define EPARTS  4           // edge-split factor for pass2
#define EPN     (NV/EPARTS) // 64 edges per part

#define S1      32          // split-K for GEMM1
#define KC1     (NUFT_DIM/S1)   // 132
#define S2      32
#define KC2     (HID/S2)        // 32

// -------- device scratch (no allocations allowed) --------
__device__ float2 g_cx[NB][NV][FX];     // e^{-i pi kx vx}
__device__ float2 g_cy[NB][NV][FYH];    // e^{-i pi ky vy}
__device__ float4 g_pvc[NB][NV];        // (pi*vx, pi*vy, -2048*C, 0)
__device__ float  g_f2T[EPARTS][NUFT_DIM][NB];   // partial spectra, transposed
__device__ float  g_featT[NUFT_DIM][NB];         // summed, transposed (k-major)
__device__ float  g_hT[HID][NB];                 // hidden, transposed (j-major)
__device__ float  g_p1[S1][NB][HID];
__device__ float  g_p2[S2][NB][OUTD];

__device__ __forceinline__ float frcp(float x) {
    float r; asm("rcp.approx.ftz.f32 %0, %1;" : "=f"(r) : "f"(x)); return r;
}
__device__ __forceinline__ unsigned long long pack2(float w) {
    unsigned int u = __float_as_uint(w);
    unsigned long long d;
    asm("mov.b64 %0, {%1, %1};" : "=l"(d) : "r"(u));
    return d;
}
#define FMA2(d, a, b) asm("fma.rn.f32x2 %0, %1, %2, %0;" : "+l"(d) : "l"(a), "l"(b))
__device__ __forceinline__ void unpack2(unsigned long long d, float& lo, float& hi) {
    unsigned int a, b;
    asm("mov.b64 {%0, %1}, %2;" : "=r"(a), "=r"(b) : "l"(d));
    lo = __uint_as_float(a); hi = __uint_as_float(b);
}

// ============================================================
// Pass 1: one thread per table entry. t -> (b, n, k), k in [0,97)
// ============================================================
__global__ __launch_bounds__(256) void pass1_kernel(const float* __restrict__ P) {
    int t = blockIdx.x * 256 + threadIdx.x;
    if (t >= NB * NV * 97) return;
    int bn = t / 97;
    int k  = t - bn * 97;
    int b = bn >> 8, n = bn & 255;
    const float PI = 3.14159265358979323846f;

    float vx = P[bn * 2], vy = P[bn * 2 + 1];

    if (k < 64) {
        int kk = (k < 32) ? k : k - 64;
        float s = (PI * (float)kk) * vx;
        float sn, cs; sincosf(s, &sn, &cs);
        g_cx[b][n][k] = make_float2(cs, -sn);
    } else {
        int y = k - 64;
        float s = (PI * (float)y) * vy;
        float sn, cs; sincosf(s, &sn, &cs);
        g_cy[b][n][y] = make_float2(cs, -sn);
        if (y == 32) {
            int n1 = (n + 1) & 255;
            float wx = P[(b * NV + n1) * 2], wy = P[(b * NV + n1) * 2 + 1];
            float C = 0.5f * (vx * wy - vy * wx);
            g_pvc[b][n] = make_float4(PI * vx, PI * vy, -2048.0f * C, 0.0f);
        }
    }
}

// exact reference semantics when a denominator is 0 (rare path)
__device__ __noinline__ void slow_S(float sa, float2 ea, float sb, float2 eb,
                                    float& Sr, float& Si) {
    float dab = sa - sb;
    float den1 = dab * sa;
    float den2 = -dab * sb;
    float den3 = sa * sb;
    Sr = 0.f; Si = 0.f;
    if (den1 != 0.f) { float r = frcp(den1); Sr += ea.x * r; Si += ea.y * r; }
    if (den2 != 0.f) { float r = frcp(den2); Sr += eb.x * r; Si += eb.y * r; }
    if (den3 != 0.f) { float r = frcp(den3); Sr += r; }
}

// ============================================================
// Pass 2: NUFT spectrum -> transposed partial feats
// block = 96 threads over linear bins, grid = (22, NB, EPARTS)
// ============================================================
__global__ __launch_bounds__(96) void pass2_kernel() {
    int bin = blockIdx.x * 96 + threadIdx.x;   // 0..2111
    int x = bin / FYH;
    int y = bin - x * FYH;
    int b = blockIdx.y;
    int part = blockIdx.z;
    int n0 = part * EPN;

    float kxf = (float)((x < 32) ? x : x - 64);
    float kyf = (float)y;

    const float2* __restrict__ cxb = &g_cx[b][0][x];   // stride FX float2
    const float2* __restrict__ cyb = &g_cy[b][0][y];   // stride FYH float2
    const float4* __restrict__ pvb = g_pvc[b];

    // carry = vertex n0-1 (mod NV)
    int np = (n0 + NV - 1) & (NV - 1);
    float4 pvp = pvb[np];
    float  sp  = fmaf(kxf, pvp.x, kyf * pvp.y);
    float2 a   = cxb[np * FX];
    float2 bb  = cyb[np * FYH];
    float2 ep  = make_float2(a.x * bb.x - a.y * bb.y, a.x * bb.y + a.y * bb.x);
    float  Cprev = pvp.z;

    float accR = 0.f, accI = 0.f;

    #pragma unroll 2
    for (int g = 0; g < EPN / 4; g++) {
        int n = n0 + 4 * g;

        float  sv[4], Cv[4];
        float2 ev[4];
        #pragma unroll
        for (int j = 0; j < 4; j++) {
            float4 pv = pvb[n + j];
            sv[j] = fmaf(kxf, pv.x, kyf * pv.y);
            Cv[j] = pv.z;
            float2 cx = cxb[(n + j) * FX];
            float2 cy = cyb[(n + j) * FYH];
            ev[j] = make_float2(fmaf(cx.x, cy.x, -cx.y * cy.y),
                                fmaf(cx.x, cy.y,  cx.y * cy.x));
        }

        float sa[4], sb[4];
        float2 ea[4], eb[4];
        sa[0] = sp;    ea[0] = ep;    sb[0] = sv[0]; eb[0] = ev[0];
        sa[1] = sv[0]; ea[1] = ev[0]; sb[1] = sv[1]; eb[1] = ev[1];
        sa[2] = sv[1]; ea[2] = ev[1]; sb[2] = sv[2]; eb[2] = ev[2];
        sa[3] = sv[2]; ea[3] = ev[2]; sb[3] = sv[3]; eb[3] = ev[3];
        float Ce[4] = { Cprev, Cv[0], Cv[1], Cv[2] };

        float d[4], nr[4], ni[4];
        #pragma unroll
        for (int j = 0; j < 4; j++) {
            float dab = sa[j] - sb[j];
            d[j]  = dab * sa[j] * sb[j];
            float tr = ea[j].x * sb[j];
            tr = fmaf(-eb[j].x, sa[j], tr);
            nr[j] = tr + dab;
            float ti = ea[j].y * sb[j];
            ni[j] = fmaf(-eb[j].y, sa[j], ti);
        }

        // Montgomery batch inversion: 1 RCP for 4 denominators
        float p01  = d[0] * d[1];
        float p012 = p01 * d[2];
        float p    = p012 * d[3];
        if (fabsf(p) > 1e-30f) {
            float r   = frcp(p);
            float i3  = r * p012;
            float t2  = r * d[3];
            float i2  = t2 * p01;
            float t1  = t2 * d[2];
            float i1  = t1 * d[0];
            float i0  = t1 * d[1];
            float w0 = Ce[0] * i0, w1 = Ce[1] * i1, w2 = Ce[2] * i2, w3 = Ce[3] * i3;
            accR = fmaf(nr[0], w0, accR); accI = fmaf(ni[0], w0, accI);
            accR = fmaf(nr[1], w1, accR); accI = fmaf(ni[1], w1, accI);
            accR = fmaf(nr[2], w2, accR); accI = fmaf(ni[2], w2, accI);
            accR = fmaf(nr[3], w3, accR); accI = fmaf(ni[3], w3, accI);
        } else {
            #pragma unroll
            for (int j = 0; j < 4; j++) {
                float Sr, Si;
                if (d[j] != 0.f) {
                    float r = frcp(d[j]);
                    Sr = nr[j] * r; Si = ni[j] * r;
                } else {
                    slow_S(sa[j], ea[j], sb[j], eb[j], Sr, Si);
                }
                accR = fmaf(Sr, Ce[j], accR);
                accI = fmaf(Si, Ce[j], accI);
            }
        }

        sp = sv[3]; ep = ev[3]; Cprev = Cv[3];
    }

    g_f2T[part][bin * 2][b]     = accR;   // scale folded into C
    g_f2T[part][bin * 2 + 1][b] = accI;
}

// ============================================================
// Sum partials: featT[k][m] = sum_p f2T[p][k][m]   (fully coalesced)
// ============================================================
__global__ __launch_bounds__(256) void sumfeat_kernel() {
    int t = blockIdx.x * 256 + threadIdx.x;   // 0 .. NUFT_DIM*NB-1
    const float* f0 = &g_f2T[0][0][0];
    float a = f0[t] + f0[t + NUFT_DIM * NB] + f0[t + 2 * NUFT_DIM * NB]
            + f0[t + 3 * NUFT_DIM * NB];
    (&g_featT[0][0])[t] = a;
}

// ============================================================
// GEMM1 (split-K, FFMA2, vectorized W):
//   block = 128 threads: lane -> j-quad (float4 of W1), warp -> m-octet
//   grid = (HID/128 = 8 j-tiles, S1)
// ============================================================
__global__ __launch_bounds__(128) void gemm1_kernel(const float* __restrict__ W1) {
    __shared__ float sh[KC1 * 32];
    int lane = threadIdx.x & 31;
    int mq   = threadIdx.x >> 5;              // m-octet: m in [8*mq, 8*mq+8)
    int s  = blockIdx.y;
    int j  = (blockIdx.x * 32 + lane) * 4;    // 4 consecutive columns
    int k0 = s * KC1;

    const float* src = &g_featT[k0][0];       // linear: k*32+m
    for (int idx = threadIdx.x; idx < KC1 * 32; idx += 128)
        sh[idx] = src[idx];
    __syncthreads();

    unsigned long long acc[16];               // [pair p][col c] = acc[p*4+c]
    #pragma unroll
    for (int q = 0; q < 16; q++) acc[q] = 0ull;

    const float4* wp = (const float4*)(W1 + (size_t)k0 * HID + j);
    #pragma unroll 4
    for (int k = 0; k < KC1; k++) {
        float4 w = wp[(size_t)k * (HID / 4)];
        unsigned long long w0 = pack2(w.x), w1 = pack2(w.y);
        unsigned long long w2 = pack2(w.z), w3 = pack2(w.w);
        const unsigned long long* row =
            (const unsigned long long*)(sh + k * 32 + mq * 8);
        #pragma unroll
        for (int p = 0; p < 4; p++) {
            unsigned long long f = row[p];    // m = mq*8+2p, +1
            FMA2(acc[p * 4 + 0], f, w0);
            FMA2(acc[p * 4 + 1], f, w1);
            FMA2(acc[p * 4 + 2], f, w2);
            FMA2(acc[p * 4 + 3], f, w3);
        }
    }

    #pragma unroll
    for (int p = 0; p < 4; p++) {
        float lo0, hi0, lo1, hi1, lo2, hi2, lo3, hi3;
        unpack2(acc[p * 4 + 0], lo0, hi0);
        unpack2(acc[p * 4 + 1], lo1, hi1);
        unpack2(acc[p * 4 + 2], lo2, hi2);
        unpack2(acc[p * 4 + 3], lo3, hi3);
        int m0 = mq * 8 + 2 * p;
        *(float4*)(&g_p1[s][m0][j])     = make_float4(lo0, lo1, lo2, lo3);
        *(float4*)(&g_p1[s][m0 + 1][j]) = make_float4(hi0, hi1, hi2, hi3);
    }
}

// epilogue 1: float2, 16384 threads; writes transposed hT[j][m]
__global__ __launch_bounds__(128) void epi1_kernel(const float* __restrict__ b1) {
    int t = blockIdx.x * 128 + threadIdx.x;   // 16384 = m*512 + j2
    int m = t >> 9, j2 = t & 511;
    int j = 2 * j2;
    float2 a = *(const float2*)(b1 + j);
    #pragma unroll
    for (int s = 0; s < S1; s++) {
        float2 p = *(const float2*)(&g_p1[s][m][j]);
        a.x += p.x; a.y += p.y;
    }
    g_hT[j][m]     = fmaxf(a.x, 0.f);
    g_hT[j + 1][m] = fmaxf(a.y, 0.f);
}

// ============================================================
// GEMM2 (split-K, FFMA2, vectorized W): grid (OUTD/128 = 4, S2), block 128
// ============================================================
__global__ __launch_bounds__(128) void gemm2_kernel(const float* __restrict__ W2) {
    __shared__ float sh[KC2 * 32];
    int lane = threadIdx.x & 31;
    int mq   = threadIdx.x >> 5;
    int s  = blockIdx.y;
    int j  = (blockIdx.x * 32 + lane) * 4;
    int k0 = s * KC2;

    const float* src = &g_hT[k0][0];
    for (int idx = threadIdx.x; idx < KC2 * 32; idx += 128)
        sh[idx] = src[idx];
    __syncthreads();

    unsigned long long acc[16];
    #pragma unroll
    for (int q = 0; q < 16; q++) acc[q] = 0ull;

    const float4* wp = (const float4*)(W2 + (size_t)k0 * OUTD + j);
    #pragma unroll 4
    for (int k = 0; k < KC2; k++) {
        float4 w = wp[(size_t)k * (OUTD / 4)];
        unsigned long long w0 = pack2(w.x), w1 = pack2(w.y);
        unsigned long long w2 = pack2(w.z), w3 = pack2(w.w);
        const unsigned long long* row =
            (const unsigned long long*)(sh + k * 32 + mq * 8);
        #pragma unroll
        for (int p = 0; p < 4; p++) {
            unsigned long long f = row[p];
            FMA2(acc[p * 4 + 0], f, w0);
            FMA2(acc[p * 4 + 1], f, w1);
            FMA2(acc[p * 4 + 2], f, w2);
            FMA2(acc[p * 4 + 3], f, w3);
        }
    }

    #pragma unroll
    for (int p = 0; p < 4; p++) {
        float lo0, hi0, lo1, hi1, lo2, hi2, lo3, hi3;
        unpack2(acc[p * 4 + 0], lo0, hi0);
        unpack2(acc[p * 4 + 1], lo1, hi1);
        unpack2(acc[p * 4 + 2], lo2, hi2);
        unpack2(acc[p * 4 + 3], lo3, hi3);
        int m0 = mq * 8 + 2 * p;
        *(float4*)(&g_p2[s][m0][j])     = make_float4(lo0, lo1, lo2, lo3);
        *(float4*)(&g_p2[s][m0 + 1][j]) = make_float4(hi0, hi1, hi2, hi3);
    }
}

// epilogue 2: float2, 8192 threads
__global__ __launch_bounds__(128) void epi2_kernel(const float* __restrict__ b2,
                                                   float* __restrict__ out) {
    int t = blockIdx.x * 128 + threadIdx.x;   // 8192 = m*256 + j2
    int m = t >> 8, j2 = t & 255;
    int j = 2 * j2;
    float2 a = *(const float2*)(b2 + j);
    #pragma unroll
    for (int s = 0; s < S2; s++) {
        float2 p = *(const float2*)(&g_p2[s][m][j]);
        a.x += p.x; a.y += p.y;
    }
    *(float2*)(out + m * OUTD + j) = a;
}

// ============================================================
extern "C" void kernel_launch(void* const* d_in, const int* in_sizes, int n_in,
                              void* d_out, int out_size) {
    const float* P  = (const float*)d_in[0];
    const float* W1 = (const float*)d_in[1];
    const float* b1 = (const float*)d_in[2];
    const float* W2 = (const float*)d_in[3];
    const float* b2 = (const float*)d_in[4];
    float* out = (float*)d_out;

    pass1_kernel<<<(NB * NV * 97 + 255) / 256, 256>>>(P);
    pass2_kernel<<<dim3(NBINS / 96, NB, EPARTS), 96>>>();
    sumfeat_kernel<<<NUFT_DIM * NB / 256, 256>>>();
    gemm1_kernel<<<dim3(HID / 128, S1), 128>>>(W1);
    epi1_kernel<<<NB * HID / 2 / 128, 128>>>(b1);
    gemm2_kernel<<<dim3(OUTD / 128, S2), 128>>>(W2);
    epi2_kernel<<<NB * OUTD / 2 / 128, 128>>>(b2, out);
}

// round 7
// speedup vs baseline: 2.3125x; 1.1309x over previous
#include <cuda_runtime.h>
#include <math.h>

#define NB      32          // batch
#define NV      256         // vertices per polygon
#define FX      64
#define FYH     33          // FY/2+1
#define NBINS   (FX*FYH)    // 2112
#define NUFT_DIM (NBINS*2)  // 4224
#define HID     1024
#define OUTD    512

#define EPARTS  4           // edge-split factor for pass2
#define EPN     (NV/EPARTS) // 64 edges per part

#define S1      66          // split-K for GEMM1
#define KC1     (NUFT_DIM/S1)   // 64
#define S2      64
#define KC2     (HID/S2)        // 16

// -------- device scratch (no allocations allowed) --------
__device__ float2 g_cx[NB][NV][FX];     // e^{-i pi kx vx}
__device__ float2 g_cy[NB][NV][FYH];    // e^{-i pi ky vy}
__device__ float4 g_pvc[NB][NV];        // (pi*vx, pi*vy, -2048*C, 0)
__device__ float  g_f2T[EPARTS][NUFT_DIM][NB];   // partial spectra, transposed
__device__ float  g_featT[NUFT_DIM][NB];         // summed, transposed (k-major)
__device__ float  g_hT[HID][NB];                 // hidden, transposed (j-major)
__device__ float  g_p1[S1][NB][HID];
__device__ float  g_p2[S2][NB][OUTD];

__device__ __forceinline__ float frcp(float x) {
    float r; asm("rcp.approx.ftz.f32 %0, %1;" : "=f"(r) : "f"(x)); return r;
}
__device__ __forceinline__ unsigned long long pack2(float w) {
    unsigned int u = __float_as_uint(w);
    unsigned long long d;
    asm("mov.b64 %0, {%1, %1};" : "=l"(d) : "r"(u));
    return d;
}
#define FMA2(d, a, b) asm("fma.rn.f32x2 %0, %1, %2, %0;" : "+l"(d) : "l"(a), "l"(b))
__device__ __forceinline__ void unpack2(unsigned long long d, float& lo, float& hi) {
    unsigned int a, b;
    asm("mov.b64 {%0, %1}, %2;" : "=r"(a), "=r"(b) : "l"(d));
    lo = __uint_as_float(a); hi = __uint_as_float(b);
}

// ============================================================
// Pass 1: one thread per table entry. t -> (b, n, k), k in [0,97)
// ============================================================
__global__ __launch_bounds__(256) void pass1_kernel(const float* __restrict__ P) {
    int t = blockIdx.x * 256 + threadIdx.x;
    if (t >= NB * NV * 97) return;
    int bn = t / 97;
    int k  = t - bn * 97;
    int b = bn >> 8, n = bn & 255;
    const float PI = 3.14159265358979323846f;

    float vx = P[bn * 2], vy = P[bn * 2 + 1];

    if (k < 64) {
        int kk = (k < 32) ? k : k - 64;
        float s = (PI * (float)kk) * vx;
        float sn, cs; sincosf(s, &sn, &cs);
        g_cx[b][n][k] = make_float2(cs, -sn);
    } else {
        int y = k - 64;
        float s = (PI * (float)y) * vy;
        float sn, cs; sincosf(s, &sn, &cs);
        g_cy[b][n][y] = make_float2(cs, -sn);
        if (y == 32) {
            int n1 = (n + 1) & 255;
            float wx = P[(b * NV + n1) * 2], wy = P[(b * NV + n1) * 2 + 1];
            float C = 0.5f * (vx * wy - vy * wx);
            g_pvc[b][n] = make_float4(PI * vx, PI * vy, -2048.0f * C, 0.0f);
        }
    }
}

// exact reference semantics when a denominator is 0 (rare path)
__device__ __noinline__ void slow_S(float sa, float2 ea, float sb, float2 eb,
                                    float& Sr, float& Si) {
    float dab = sa - sb;
    float den1 = dab * sa;
    float den2 = -dab * sb;
    float den3 = sa * sb;
    Sr = 0.f; Si = 0.f;
    if (den1 != 0.f) { float r = frcp(den1); Sr += ea.x * r; Si += ea.y * r; }
    if (den2 != 0.f) { float r = frcp(den2); Sr += eb.x * r; Si += eb.y * r; }
    if (den3 != 0.f) { float r = frcp(den3); Sr += r; }
}

// ============================================================
// Pass 2: NUFT spectrum -> transposed partial feats
// block = 96 threads over linear bins, grid = (22, NB, EPARTS)
// ============================================================
__global__ __launch_bounds__(96) void pass2_kernel() {
    int bin = blockIdx.x * 96 + threadIdx.x;   // 0..2111
    int x = bin / FYH;
    int y = bin - x * FYH;
    int b = blockIdx.y;
    int part = blockIdx.z;
    int n0 = part * EPN;

    float kxf = (float)((x < 32) ? x : x - 64);
    float kyf = (float)y;

    const float2* __restrict__ cxb = &g_cx[b][0][x];   // stride FX float2
    const float2* __restrict__ cyb = &g_cy[b][0][y];   // stride FYH float2
    const float4* __restrict__ pvb = g_pvc[b];

    // carry = vertex n0-1 (mod NV)
    int np = (n0 + NV - 1) & (NV - 1);
    float4 pvp = pvb[np];
    float  sp  = fmaf(kxf, pvp.x, kyf * pvp.y);
    float2 a   = cxb[np * FX];
    float2 bb  = cyb[np * FYH];
    float2 ep  = make_float2(a.x * bb.x - a.y * bb.y, a.x * bb.y + a.y * bb.x);
    float  Cprev = pvp.z;

    float accR = 0.f, accI = 0.f;

    #pragma unroll 2
    for (int g = 0; g < EPN / 4; g++) {
        int n = n0 + 4 * g;

        float  sv[4], Cv[4];
        float2 ev[4];
        #pragma unroll
        for (int j = 0; j < 4; j++) {
            float4 pv = pvb[n + j];
            sv[j] = fmaf(kxf, pv.x, kyf * pv.y);
            Cv[j] = pv.z;
            float2 cx = cxb[(n + j) * FX];
            float2 cy = cyb[(n + j) * FYH];
            ev[j] = make_float2(fmaf(cx.x, cy.x, -cx.y * cy.y),
                                fmaf(cx.x, cy.y,  cx.y * cy.x));
        }

        float sa[4], sb[4];
        float2 ea[4], eb[4];
        sa[0] = sp;    ea[0] = ep;    sb[0] = sv[0]; eb[0] = ev[0];
        sa[1] = sv[0]; ea[1] = ev[0]; sb[1] = sv[1]; eb[1] = ev[1];
        sa[2] = sv[1]; ea[2] = ev[1]; sb[2] = sv[2]; eb[2] = ev[2];
        sa[3] = sv[2]; ea[3] = ev[2]; sb[3] = sv[3]; eb[3] = ev[3];
        float Ce[4] = { Cprev, Cv[0], Cv[1], Cv[2] };

        float d[4], nr[4], ni[4];
        #pragma unroll
        for (int j = 0; j < 4; j++) {
            float dab = sa[j] - sb[j];
            d[j]  = dab * sa[j] * sb[j];
            float tr = ea[j].x * sb[j];
            tr = fmaf(-eb[j].x, sa[j], tr);
            nr[j] = tr + dab;
            float ti = ea[j].y * sb[j];
            ni[j] = fmaf(-eb[j].y, sa[j], ti);
        }

        // Montgomery batch inversion: 1 RCP for 4 denominators
        float p01  = d[0] * d[1];
        float p012 = p01 * d[2];
        float p    = p012 * d[3];
        if (fabsf(p) > 1e-30f) {
            float r   = frcp(p);
            float i3  = r * p012;
            float t2  = r * d[3];
            float i2  = t2 * p01;
            float t1  = t2 * d[2];
            float i1  = t1 * d[0];
            float i0  = t1 * d[1];
            float w0 = Ce[0] * i0, w1 = Ce[1] * i1, w2 = Ce[2] * i2, w3 = Ce[3] * i3;
            accR = fmaf(nr[0], w0, accR); accI = fmaf(ni[0], w0, accI);
            accR = fmaf(nr[1], w1, accR); accI = fmaf(ni[1], w1, accI);
            accR = fmaf(nr[2], w2, accR); accI = fmaf(ni[2], w2, accI);
            accR = fmaf(nr[3], w3, accR); accI = fmaf(ni[3], w3, accI);
        } else {
            #pragma unroll
            for (int j = 0; j < 4; j++) {
                float Sr, Si;
                if (d[j] != 0.f) {
                    float r = frcp(d[j]);
                    Sr = nr[j] * r; Si = ni[j] * r;
                } else {
                    slow_S(sa[j], ea[j], sb[j], eb[j], Sr, Si);
                }
                accR = fmaf(Sr, Ce[j], accR);
                accI = fmaf(Si, Ce[j], accI);
            }
        }

        sp = sv[3]; ep = ev[3]; Cprev = Cv[3];
    }

    g_f2T[part][bin * 2][b]     = accR;   // scale folded into C
    g_f2T[part][bin * 2 + 1][b] = accI;
}

// ============================================================
// Sum partials: featT[k][m] = sum_p f2T[p][k][m]   (fully coalesced)
// ============================================================
__global__ __launch_bounds__(256) void sumfeat_kernel() {
    int t = blockIdx.x * 256 + threadIdx.x;   // 0 .. NUFT_DIM*NB-1
    const float* f0 = &g_f2T[0][0][0];
    float a = f0[t] + f0[t + NUFT_DIM * NB] + f0[t + 2 * NUFT_DIM * NB]
            + f0[t + 3 * NUFT_DIM * NB];
    (&g_featT[0][0])[t] = a;
}

// ============================================================
// GEMM1 (split-K, FFMA2, double-buffered W prefetch):
//   block = 128: lane -> j-quad, warp -> m-octet; grid (8, S1=66)
// ============================================================
__global__ __launch_bounds__(128) void gemm1_kernel(const float* __restrict__ W1) {
    __shared__ float sh[KC1 * 32];            // 64*32 floats = 8KB
    int lane = threadIdx.x & 31;
    int mq   = threadIdx.x >> 5;
    int s  = blockIdx.y;
    int j  = (blockIdx.x * 32 + lane) * 4;
    int k0 = s * KC1;

    {
        const float4* s4 = (const float4*)&g_featT[k0][0];
        float4* d4 = (float4*)sh;
        #pragma unroll
        for (int i = 0; i < KC1 * 32 / 4 / 128; i++)
            d4[threadIdx.x + i * 128] = s4[threadIdx.x + i * 128];
    }
    __syncthreads();

    unsigned long long acc[16];
    #pragma unroll
    for (int q = 0; q < 16; q++) acc[q] = 0ull;

    const float4* wp = (const float4*)(W1 + (size_t)k0 * HID + j);
    const int wstride = HID / 4;

    float4 wa[4], wb[4];
    #pragma unroll
    for (int u = 0; u < 4; u++) wa[u] = wp[u * wstride];

    #pragma unroll 1
    for (int kb = 0; kb < KC1; kb += 4) {
        if (kb + 4 < KC1) {
            #pragma unroll
            for (int u = 0; u < 4; u++) wb[u] = wp[(kb + 4 + u) * wstride];
        }
        #pragma unroll
        for (int u = 0; u < 4; u++) {
            unsigned long long w0 = pack2(wa[u].x), w1 = pack2(wa[u].y);
            unsigned long long w2 = pack2(wa[u].z), w3 = pack2(wa[u].w);
            const unsigned long long* row =
                (const unsigned long long*)(sh + (kb + u) * 32 + mq * 8);
            #pragma unroll
            for (int p = 0; p < 4; p++) {
                unsigned long long f = row[p];
                FMA2(acc[p * 4 + 0], f, w0);
                FMA2(acc[p * 4 + 1], f, w1);
                FMA2(acc[p * 4 + 2], f, w2);
                FMA2(acc[p * 4 + 3], f, w3);
            }
        }
        #pragma unroll
        for (int u = 0; u < 4; u++) wa[u] = wb[u];
    }

    #pragma unroll
    for (int p = 0; p < 4; p++) {
        float lo0, hi0, lo1, hi1, lo2, hi2, lo3, hi3;
        unpack2(acc[p * 4 + 0], lo0, hi0);
        unpack2(acc[p * 4 + 1], lo1, hi1);
        unpack2(acc[p * 4 + 2], lo2, hi2);
        unpack2(acc[p * 4 + 3], lo3, hi3);
        int m0 = mq * 8 + 2 * p;
        *(float4*)(&g_p1[s][m0][j])     = make_float4(lo0, lo1, lo2, lo3);
        *(float4*)(&g_p1[s][m0 + 1][j]) = make_float4(hi0, hi1, hi2, hi3);
    }
}

// epilogue 1: float2, 16384 threads; writes transposed hT[j][m]
__global__ __launch_bounds__(128) void epi1_kernel(const float* __restrict__ b1) {
    int t = blockIdx.x * 128 + threadIdx.x;   // 16384 = m*512 + j2
    int m = t >> 9, j2 = t & 511;
    int j = 2 * j2;
    float2 a = *(const float2*)(b1 + j);
    #pragma unroll 11
    for (int s = 0; s < S1; s++) {
        float2 p = *(const float2*)(&g_p1[s][m][j]);
        a.x += p.x; a.y += p.y;
    }
    g_hT[j][m]     = fmaxf(a.x, 0.f);
    g_hT[j + 1][m] = fmaxf(a.y, 0.f);
}

// ============================================================
// GEMM2 (split-K, FFMA2, double-buffered): grid (4, S2=64), block 128
// ============================================================
__global__ __launch_bounds__(128) void gemm2_kernel(const float* __restrict__ W2) {
    __shared__ float sh[KC2 * 32];            // 16*32 floats = 2KB
    int lane = threadIdx.x & 31;
    int mq   = threadIdx.x >> 5;
    int s  = blockIdx.y;
    int j  = (blockIdx.x * 32 + lane) * 4;
    int k0 = s * KC2;

    {
        const float4* s4 = (const float4*)&g_hT[k0][0];
        float4* d4 = (float4*)sh;
        if (threadIdx.x < KC2 * 32 / 4) d4[threadIdx.x] = s4[threadIdx.x];
    }
    __syncthreads();

    unsigned long long acc[16];
    #pragma unroll
    for (int q = 0; q < 16; q++) acc[q] = 0ull;

    const float4* wp = (const float4*)(W2 + (size_t)k0 * OUTD + j);
    const int wstride = OUTD / 4;

    float4 wa[4], wb[4];
    #pragma unroll
    for (int u = 0; u < 4; u++) wa[u] = wp[u * wstride];

    #pragma unroll 1
    for (int kb = 0; kb < KC2; kb += 4) {
        if (kb + 4 < KC2) {
            #pragma unroll
            for (int u = 0; u < 4; u++) wb[u] = wp[(kb + 4 + u) * wstride];
        }
        #pragma unroll
        for (int u = 0; u < 4; u++) {
            unsigned long long w0 = pack2(wa[u].x), w1 = pack2(wa[u].y);
            unsigned long long w2 = pack2(wa[u].z), w3 = pack2(wa[u].w);
            const unsigned long long* row =
                (const unsigned long long*)(sh + (kb + u) * 32 + mq * 8);
            #pragma unroll
            for (int p = 0; p < 4; p++) {
                unsigned long long f = row[p];
                FMA2(acc[p * 4 + 0], f, w0);
                FMA2(acc[p * 4 + 1], f, w1);
                FMA2(acc[p * 4 + 2], f, w2);
                FMA2(acc[p * 4 + 3], f, w3);
            }
        }
        #pragma unroll
        for (int u = 0; u < 4; u++) wa[u] = wb[u];
    }

    #pragma unroll
    for (int p = 0; p < 4; p++) {
        float lo0, hi0, lo1, hi1, lo2, hi2, lo3, hi3;
        unpack2(acc[p * 4 + 0], lo0, hi0);
        unpack2(acc[p * 4 + 1], lo1, hi1);
        unpack2(acc[p * 4 + 2], lo2, hi2);
        unpack2(acc[p * 4 + 3], lo3, hi3);
        int m0 = mq * 8 + 2 * p;
        *(float4*)(&g_p2[s][m0][j])     = make_float4(lo0, lo1, lo2, lo3);
        *(float4*)(&g_p2[s][m0 + 1][j]) = make_float4(hi0, hi1, hi2, hi3);
    }
}

// epilogue 2: float2, 8192 threads
__global__ __launch_bounds__(128) void epi2_kernel(const float* __restrict__ b2,
                                                   float* __restrict__ out) {
    int t = blockIdx.x * 128 + threadIdx.x;   // 8192 = m*256 + j2
    int m = t >> 8, j2 = t & 255;
    int j = 2 * j2;
    float2 a = *(const float2*)(b2 + j);
    #pragma unroll 16
    for (int s = 0; s < S2; s++) {
        float2 p = *(const float2*)(&g_p2[s][m][j]);
        a.x += p.x; a.y += p.y;
    }
    *(float2*)(out + m * OUTD + j) = a;
}

// ============================================================
extern "C" void kernel_launch(void* const* d_in, const int* in_sizes, int n_in,
                              void* d_out, int out_size) {
    const float* P  = (const float*)d_in[0];
    const float* W1 = (const float*)d_in[1];
    const float* b1 = (const float*)d_in[2];
    const float* W2 = (const float*)d_in[3];
    const float* b2 = (const float*)d_in[4];
    float* out = (float*)d_out;

    pass1_kernel<<<(NB * NV * 97 + 255) / 256, 256>>>(P);
    pass2_kernel<<<dim3(NBINS / 96, NB, EPARTS), 96>>>();
    sumfeat_kernel<<<NUFT_DIM * NB / 256, 256>>>();
    gemm1_kernel<<<dim3(HID / 128, S1), 128>>>(W1);
    epi1_kernel<<<NB * HID / 2 / 128, 128>>>(b1);
    gemm2_kernel<<<dim3(OUTD / 128, S2), 128>>>(W2);
    epi2_kernel<<<NB * OUTD / 2 / 128, 128>>>(b2, out);
}